// round 1
// baseline (speedup 1.0000x reference)
#include <cuda_runtime.h>
#include <math.h>

// Problem constants (fixed shapes)
#define BB 8
#define HH 64
#define WW 64
#define CC 256
#define NPIX (BB*HH*WW)          // 32768

// Scratch (allocation-free rule: __device__ globals)
__device__ float g_W[CC*CC];                 // fused weight: W[e,c] = sum_d proj_w[e,d]*v_w[d,c]
__device__ float g_y[NPIX*CC];               // blurred x

// ---------------------------------------------------------------------------
// K1: W = proj_w @ v_w   (NN GEMM, M=N=K=256), 64x64 tiles, 256 threads, TM=TN=4
// ---------------------------------------------------------------------------
__global__ __launch_bounds__(256) void fuse_w_kernel(const float* __restrict__ P,
                                                     const float* __restrict__ V) {
    __shared__ float As[16][64];
    __shared__ float Bs[16][68];   // pad to dodge conflicts
    int tid = threadIdx.x;
    int bm = blockIdx.y * 64, bn = blockIdx.x * 64;
    int ar = tid >> 2, akc = (tid & 3) * 4;      // A tile 64x16
    int bk = tid >> 4, bc = (tid & 15) * 4;      // B tile 16x64
    int tx = tid & 15, ty = tid >> 4;
    float acc[4][4] = {};
    for (int k0 = 0; k0 < 256; k0 += 16) {
        float4 a = *(const float4*)(P + (bm + ar) * 256 + k0 + akc);
        As[akc + 0][ar] = a.x; As[akc + 1][ar] = a.y;
        As[akc + 2][ar] = a.z; As[akc + 3][ar] = a.w;
        float4 b = *(const float4*)(V + (k0 + bk) * 256 + bn + bc);
        Bs[bk][bc + 0] = b.x; Bs[bk][bc + 1] = b.y;
        Bs[bk][bc + 2] = b.z; Bs[bk][bc + 3] = b.w;
        __syncthreads();
        #pragma unroll
        for (int k = 0; k < 16; k++) {
            float ar4[4], br4[4];
            #pragma unroll
            for (int i = 0; i < 4; i++) ar4[i] = As[k][ty * 4 + i];
            #pragma unroll
            for (int j = 0; j < 4; j++) br4[j] = Bs[k][tx * 4 + j];
            #pragma unroll
            for (int i = 0; i < 4; i++)
                #pragma unroll
                for (int j = 0; j < 4; j++) acc[i][j] += ar4[i] * br4[j];
        }
        __syncthreads();
    }
    #pragma unroll
    for (int i = 0; i < 4; i++) {
        float4 o = make_float4(acc[i][0], acc[i][1], acc[i][2], acc[i][3]);
        *(float4*)(g_W + (bm + ty * 4 + i) * 256 + bn + tx * 4) = o;
    }
}

// ---------------------------------------------------------------------------
// K2: 3x3 blur. Weight e/(e+8) at tap (i=0,j=0) i.e. x[h-1,w-1]; 1/(e+8) else.
// One thread per (pixel, float4-channel-chunk).
// ---------------------------------------------------------------------------
__global__ __launch_bounds__(256) void blur_kernel(const float* __restrict__ x) {
    int t = blockIdx.x * 256 + threadIdx.x;      // 0 .. NPIX*64-1
    int c4 = t & 63;
    int p  = t >> 6;
    int w  = p & 63;
    int hb = p >> 6;
    int h  = hb & 63;
    int b  = hb >> 6;
    const float e  = expf(1.0f);
    const float wo = 1.0f / (e + 8.0f);
    const float ws = e * wo;
    const float4* x4 = (const float4*)x;
    float4 acc = make_float4(0.f, 0.f, 0.f, 0.f);
    #pragma unroll
    for (int i = 0; i < 3; i++) {
        int hh = h + i - 1;
        if (hh < 0 || hh >= HH) continue;
        #pragma unroll
        for (int j = 0; j < 3; j++) {
            int ww = w + j - 1;
            if (ww < 0 || ww >= WW) continue;
            float wgt = (i == 0 && j == 0) ? ws : wo;
            float4 v = x4[((b * HH + hh) * WW + ww) * 64 + c4];
            acc.x += wgt * v.x; acc.y += wgt * v.y;
            acc.z += wgt * v.z; acc.w += wgt * v.w;
        }
    }
    ((float4*)g_y)[t] = acc;
}

// ---------------------------------------------------------------------------
// K3: out[m,n] = sum_k y[m,k]*W[n,k] + bias[n]  (NT GEMM, M=32768,N=256,K=256)
// 128x128x8 tiles, 256 threads, 8x8 per thread.
// ---------------------------------------------------------------------------
__global__ __launch_bounds__(256) void gemm_nt_kernel(const float* __restrict__ bias,
                                                      float* __restrict__ C) {
    __shared__ float As[8][128];
    __shared__ float Bs[8][128];
    int tid = threadIdx.x;
    int bm = blockIdx.y * 128;
    int bn = blockIdx.x * 128;
    int lr = tid >> 1;            // 0..127
    int lc = (tid & 1) * 4;       // 0 or 4
    int tx = tid & 15, ty = tid >> 4;
    float acc[8][8] = {};
    const float* Ag = g_y + (size_t)(bm + lr) * 256 + lc;
    const float* Bg = g_W + (size_t)(bn + lr) * 256 + lc;
    for (int k0 = 0; k0 < 256; k0 += 8) {
        float4 a  = *(const float4*)(Ag + k0);
        float4 bv = *(const float4*)(Bg + k0);
        As[lc + 0][lr] = a.x;  As[lc + 1][lr] = a.y;
        As[lc + 2][lr] = a.z;  As[lc + 3][lr] = a.w;
        Bs[lc + 0][lr] = bv.x; Bs[lc + 1][lr] = bv.y;
        Bs[lc + 2][lr] = bv.z; Bs[lc + 3][lr] = bv.w;
        __syncthreads();
        #pragma unroll
        for (int k = 0; k < 8; k++) {
            float a8[8], b8[8];
            #pragma unroll
            for (int i = 0; i < 8; i++) a8[i] = As[k][ty * 8 + i];
            #pragma unroll
            for (int j = 0; j < 8; j++) b8[j] = Bs[k][tx * 8 + j];
            #pragma unroll
            for (int i = 0; i < 8; i++)
                #pragma unroll
                for (int j = 0; j < 8; j++) acc[i][j] += a8[i] * b8[j];
        }
        __syncthreads();
    }
    #pragma unroll
    for (int i = 0; i < 8; i++) {
        int m = bm + ty * 8 + i;
        #pragma unroll
        for (int j = 0; j < 8; j += 4) {
            int n = bn + tx * 8 + j;
            float4 o;
            o.x = acc[i][j + 0] + bias[n + 0];
            o.y = acc[i][j + 1] + bias[n + 1];
            o.z = acc[i][j + 2] + bias[n + 2];
            o.w = acc[i][j + 3] + bias[n + 3];
            *(float4*)(C + (size_t)m * 256 + n) = o;
        }
    }
}

extern "C" void kernel_launch(void* const* d_in, const int* in_sizes, int n_in,
                              void* d_out, int out_size) {
    const float* x  = (const float*)d_in[0];   // [8,64,64,256]
    const float* vw = (const float*)d_in[1];   // [256,256] (d,c)
    const float* pw = (const float*)d_in[2];   // [256,256] (e,d)
    const float* pb = (const float*)d_in[3];   // [256]
    float* out = (float*)d_out;                // [8,64,64,256]

    // K1: fused weight W = proj_w @ v_w
    fuse_w_kernel<<<dim3(4, 4), 256>>>(pw, vw);
    // K2: blur x -> g_y (independent of K1; serialized on stream, cheap)
    blur_kernel<<<(NPIX * 64) / 256, 256>>>(x);
    // K3: out = g_y @ W^T + b
    gemm_nt_kernel<<<dim3(2, 256), 256>>>(pb, out);
}

// round 3
// speedup vs baseline: 1.3224x; 1.3224x over previous
#include <cuda_runtime.h>
#include <cuda_bf16.h>
#include <stdint.h>
#include <math.h>

#define BB 8
#define HH 64
#define WW 64
#define CC 256
#define NPIX (BB*HH*WW)          // 32768

// ---------------- device scratch (allocation-free rule) ----------------
__device__ __nv_bfloat16 g_yhi[NPIX*CC];   // blurred x, hi bf16
__device__ __nv_bfloat16 g_ylo[NPIX*CC];   // blurred x, lo bf16
__device__ __nv_bfloat16 g_Whi[CC*CC];     // fused weight W = proj_w @ v_w, hi
__device__ __nv_bfloat16 g_Wlo[CC*CC];     // fused weight, lo

// ---------------- helpers ----------------
__device__ __forceinline__ uint32_t smem_u32(const void* p) {
    uint32_t a;
    asm("{ .reg .u64 t; cvta.to.shared.u64 t, %1; cvt.u32.u64 %0, t; }" : "=r"(a) : "l"(p));
    return a;
}
__device__ __forceinline__ uint64_t gmem_u64(const void* p) {
    uint64_t a;
    asm("cvta.to.global.u64 %0, %1;" : "=l"(a) : "l"(p));
    return a;
}
#define CP_ASYNC16(sa, ga) \
    asm volatile("cp.async.cg.shared.global [%0], [%1], 16;" :: "r"(sa), "l"(ga))
#define CP_COMMIT() asm volatile("cp.async.commit_group;")
#define CP_WAIT(n)  asm volatile("cp.async.wait_group %0;" :: "n"(n))

#define LDMATRIX_X4(r0, r1, r2, r3, addr) \
    asm volatile("ldmatrix.sync.aligned.m8n8.x4.shared.b16 {%0,%1,%2,%3}, [%4];" \
        : "=r"(r0), "=r"(r1), "=r"(r2), "=r"(r3) : "r"(addr))

#define MMA_16816(c, a, b0, b1) \
    asm volatile("mma.sync.aligned.m16n8k16.row.col.f32.bf16.bf16.f32 " \
        "{%0,%1,%2,%3}, {%4,%5,%6,%7}, {%8,%9}, {%0,%1,%2,%3};" \
        : "+f"((c)[0]), "+f"((c)[1]), "+f"((c)[2]), "+f"((c)[3]) \
        : "r"((a)[0]), "r"((a)[1]), "r"((a)[2]), "r"((a)[3]), "r"(b0), "r"(b1))

static __device__ __forceinline__ void split_bf16(float v, __nv_bfloat16& hi, __nv_bfloat16& lo) {
    hi = __float2bfloat16_rn(v);
    lo = __float2bfloat16_rn(v - __bfloat162float(hi));
}

// ============================================================================
// K1: prep. Blocks [0,8192): 3x3 blur of x -> (g_yhi,g_ylo).
//     Blocks [8192,8256): W = proj_w @ v_w -> (g_Whi,g_Wlo).
// ============================================================================
__global__ __launch_bounds__(256) void prep_kernel(const float* __restrict__ x,
                                                   const float* __restrict__ vw,
                                                   const float* __restrict__ pw) {
    int bid = blockIdx.x;
    int tid = threadIdx.x;
    if (bid < 8192) {
        int t  = bid * 256 + tid;
        int c4 = t & 63;
        int p  = t >> 6;
        int w  = p & 63;
        int hb = p >> 6;
        int h  = hb & 63;
        int b  = hb >> 6;
        const float e  = 2.718281828459045f;
        const float wo = 1.0f / (e + 8.0f);
        const float ws = e * wo;
        const float4* x4 = (const float4*)x;
        float4 acc = make_float4(0.f, 0.f, 0.f, 0.f);
        #pragma unroll
        for (int i = 0; i < 3; i++) {
            int hh = h + i - 1;
            if (hh < 0 || hh >= HH) continue;
            #pragma unroll
            for (int j = 0; j < 3; j++) {
                int ww = w + j - 1;
                if (ww < 0 || ww >= WW) continue;
                float wgt = (i == 0 && j == 0) ? ws : wo;
                float4 v = x4[((b * HH + hh) * WW + ww) * 64 + c4];
                acc.x += wgt * v.x; acc.y += wgt * v.y;
                acc.z += wgt * v.z; acc.w += wgt * v.w;
            }
        }
        union { __nv_bfloat16 h4[4]; uint2 u; } Hi, Lo;
        split_bf16(acc.x, Hi.h4[0], Lo.h4[0]);
        split_bf16(acc.y, Hi.h4[1], Lo.h4[1]);
        split_bf16(acc.z, Hi.h4[2], Lo.h4[2]);
        split_bf16(acc.w, Hi.h4[3], Lo.h4[3]);
        ((uint2*)g_yhi)[t] = Hi.u;
        ((uint2*)g_ylo)[t] = Lo.u;
    } else {
        int q  = bid - 8192;
        int e0 = (q >> 3) * 32;
        int c0 = (q & 7) * 32;
        int er = e0 + (tid >> 3);
        int cc = c0 + (tid & 7) * 4;
        float a0 = 0.f, a1 = 0.f, a2 = 0.f, a3 = 0.f;
        const float* prow = pw + er * 256;
        #pragma unroll 8
        for (int d = 0; d < 256; d++) {
            float a = prow[d];
            float4 v = *(const float4*)(vw + d * 256 + cc);
            a0 += a * v.x; a1 += a * v.y; a2 += a * v.z; a3 += a * v.w;
        }
        union { __nv_bfloat16 h4[4]; uint2 u; } Hi, Lo;
        split_bf16(a0, Hi.h4[0], Lo.h4[0]);
        split_bf16(a1, Hi.h4[1], Lo.h4[1]);
        split_bf16(a2, Hi.h4[2], Lo.h4[2]);
        split_bf16(a3, Hi.h4[3], Lo.h4[3]);
        int idx = er * 256 + cc;
        *(uint2*)(g_Whi + idx) = Hi.u;
        *(uint2*)(g_Wlo + idx) = Lo.u;
    }
}

// ============================================================================
// K2: out[m,n] = sum_k y[m,k]*W[n,k] + bias[n]  via mma.sync bf16 (3 passes)
//     effective K = 768 over 24 chunks of 32:
//       chunk c: term = c/8  -> (A,B) = (yhi,Whi), (ylo,Whi), (yhi,Wlo)
//     CTA tile 128x128, 8 warps (4x2), warp tile 32x64, double-buffered cp.async.
//     smem row stride 80B (32 bf16 + 16B pad) -> ldmatrix conflict-free.
// ============================================================================
#define A_STAGE 10240                 // 128 rows * 80B
#define B_OFF   (2 * A_STAGE)         // B after both A stages

__global__ __launch_bounds__(256) void gemm_mma_kernel(const float* __restrict__ bias,
                                                       float* __restrict__ out) {
    __shared__ __align__(16) char smem[4 * A_STAGE];   // A0,A1,B0,B1 = 40KB
    uint32_t sb = smem_u32(smem);
    int tid  = threadIdx.x;
    int wid  = tid >> 5;
    int lane = tid & 31;
    int bn = blockIdx.x * 128;
    int bm = blockIdx.y * 128;
    int wn = wid & 1;          // 0..1 -> 64-wide N slice
    int wm = wid >> 1;         // 0..3 -> 32-wide M slice

    float acc[2][8][4] = {};

    int ldrow = tid >> 1;              // 0..127 : two 16B chunks per row handled by 2 threads
    int ldc8a = (tid & 1) * 2;         // chunk pair start (of 4 chunks per 64B row)

    // ---- pipeline ----
    #pragma unroll 1
    for (int kc = 0; kc < 24; kc++) {
        // issue loads for chunk kc on first two iterations' prologue + steady state
        if (kc == 0) {
            // prologue: load chunk 0 and 1
            #pragma unroll
            for (int pc = 0; pc < 2; pc++) {
                int term = pc >> 3, kb = (pc & 7) * 32;
                const __nv_bfloat16* sA = (term == 1) ? g_ylo : g_yhi;
                const __nv_bfloat16* sB = (term == 2) ? g_Wlo : g_Whi;
                #pragma unroll
                for (int i = 0; i < 2; i++) {
                    int c8 = ldc8a + i;
                    uint64_t ga = gmem_u64(sA + (size_t)(bm + ldrow) * 256 + kb + c8 * 8);
                    uint64_t gb = gmem_u64(sB + (size_t)(bn + ldrow) * 256 + kb + c8 * 8);
                    uint32_t da = sb + pc * A_STAGE + ldrow * 80 + c8 * 16;
                    uint32_t db = sb + B_OFF + pc * A_STAGE + ldrow * 80 + c8 * 16;
                    CP_ASYNC16(da, ga);
                    CP_ASYNC16(db, gb);
                }
                CP_COMMIT();
            }
        } else if (kc + 1 < 24) {
            int pc = kc + 1;
            int s = pc & 1;
            int term = pc >> 3, kb = (pc & 7) * 32;
            const __nv_bfloat16* sA = (term == 1) ? g_ylo : g_yhi;
            const __nv_bfloat16* sB = (term == 2) ? g_Wlo : g_Whi;
            #pragma unroll
            for (int i = 0; i < 2; i++) {
                int c8 = ldc8a + i;
                uint64_t ga = gmem_u64(sA + (size_t)(bm + ldrow) * 256 + kb + c8 * 8);
                uint64_t gb = gmem_u64(sB + (size_t)(bn + ldrow) * 256 + kb + c8 * 8);
                uint32_t da = sb + s * A_STAGE + ldrow * 80 + c8 * 16;
                uint32_t db = sb + B_OFF + s * A_STAGE + ldrow * 80 + c8 * 16;
                CP_ASYNC16(da, ga);
                CP_ASYNC16(db, gb);
            }
            CP_COMMIT();
        }

        // wait for chunk kc's data
        if (kc + 1 < 24) { CP_WAIT(1); } else { CP_WAIT(0); }
        __syncthreads();

        int s = kc & 1;
        uint32_t aBase = sb + s * A_STAGE;
        uint32_t bBase = sb + B_OFF + s * A_STAGE;

        #pragma unroll
        for (int ks = 0; ks < 2; ks++) {
            uint32_t af[2][4];
            #pragma unroll
            for (int mi = 0; mi < 2; mi++) {
                int row = wm * 32 + mi * 16 + (lane & 15);
                uint32_t addr = aBase + row * 80 + ks * 32 + (lane >> 4) * 16;
                LDMATRIX_X4(af[mi][0], af[mi][1], af[mi][2], af[mi][3], addr);
            }
            uint32_t bf[4][4];
            #pragma unroll
            for (int ng = 0; ng < 4; ng++) {
                int row = wn * 64 + ng * 16 + (lane & 15);
                uint32_t addr = bBase + row * 80 + ks * 32 + (lane >> 4) * 16;
                LDMATRIX_X4(bf[ng][0], bf[ng][1], bf[ng][2], bf[ng][3], addr);
            }
            #pragma unroll
            for (int mi = 0; mi < 2; mi++)
                #pragma unroll
                for (int ng = 0; ng < 4; ng++) {
                    MMA_16816(acc[mi][ng * 2 + 0], af[mi], bf[ng][0], bf[ng][2]);
                    MMA_16816(acc[mi][ng * 2 + 1], af[mi], bf[ng][1], bf[ng][3]);
                }
        }
        __syncthreads();   // stage consumed; safe to overwrite next iteration
    }

    // ---- epilogue ----
    #pragma unroll
    for (int mi = 0; mi < 2; mi++) {
        int r0 = bm + wm * 32 + mi * 16 + (lane >> 2);
        #pragma unroll
        for (int ni = 0; ni < 8; ni++) {
            int c = bn + wn * 64 + ni * 8 + (lane & 3) * 2;
            float b0 = __ldg(bias + c);
            float b1 = __ldg(bias + c + 1);
            float2 o0 = make_float2(acc[mi][ni][0] + b0, acc[mi][ni][1] + b1);
            float2 o1 = make_float2(acc[mi][ni][2] + b0, acc[mi][ni][3] + b1);
            *(float2*)(out + (size_t)r0 * 256 + c) = o0;
            *(float2*)(out + (size_t)(r0 + 8) * 256 + c) = o1;
        }
    }
}

// ============================================================================
extern "C" void kernel_launch(void* const* d_in, const int* in_sizes, int n_in,
                              void* d_out, int out_size) {
    const float* x  = (const float*)d_in[0];   // [8,64,64,256]
    const float* vw = (const float*)d_in[1];   // [256,256]
    const float* pw = (const float*)d_in[2];   // [256,256]
    const float* pb = (const float*)d_in[3];   // [256]
    float* out = (float*)d_out;

    prep_kernel<<<8192 + 64, 256>>>(x, vw, pw);
    gemm_mma_kernel<<<dim3(2, 256), 256>>>(pb, out);
}

// round 4
// speedup vs baseline: 1.6246x; 1.2285x over previous
#include <cuda_runtime.h>
#include <cuda_bf16.h>
#include <stdint.h>
#include <math.h>

#define BB 8
#define HH 64
#define WW 64
#define CC 256
#define NPIX (BB*HH*WW)          // 32768

// ---------------- device scratch (allocation-free rule) ----------------
__device__ __nv_bfloat16 g_yhi[NPIX*CC];
__device__ __nv_bfloat16 g_ylo[NPIX*CC];
__device__ __nv_bfloat16 g_Whi[CC*CC];
__device__ __nv_bfloat16 g_Wlo[CC*CC];

// ---------------- helpers ----------------
__device__ __forceinline__ uint32_t smem_u32(const void* p) {
    uint32_t a;
    asm("{ .reg .u64 t; cvta.to.shared.u64 t, %1; cvt.u32.u64 %0, t; }" : "=r"(a) : "l"(p));
    return a;
}
__device__ __forceinline__ uint64_t gmem_u64(const void* p) {
    uint64_t a;
    asm("cvta.to.global.u64 %0, %1;" : "=l"(a) : "l"(p));
    return a;
}
#define CP_ASYNC16(sa, ga) \
    asm volatile("cp.async.cg.shared.global [%0], [%1], 16;" :: "r"(sa), "l"(ga))
#define CP_COMMIT() asm volatile("cp.async.commit_group;")
#define CP_WAIT(n)  asm volatile("cp.async.wait_group %0;" :: "n"(n))

#define LDMATRIX_X4(r0, r1, r2, r3, addr) \
    asm volatile("ldmatrix.sync.aligned.m8n8.x4.shared.b16 {%0,%1,%2,%3}, [%4];" \
        : "=r"(r0), "=r"(r1), "=r"(r2), "=r"(r3) : "r"(addr))

#define MMA_16816(c, a, b0, b1) \
    asm volatile("mma.sync.aligned.m16n8k16.row.col.f32.bf16.bf16.f32 " \
        "{%0,%1,%2,%3}, {%4,%5,%6,%7}, {%8,%9}, {%0,%1,%2,%3};" \
        : "+f"((c)[0]), "+f"((c)[1]), "+f"((c)[2]), "+f"((c)[3]) \
        : "r"((a)[0]), "r"((a)[1]), "r"((a)[2]), "r"((a)[3]), "r"(b0), "r"(b1))

static __device__ __forceinline__ void split_bf16(float v, __nv_bfloat16& hi, __nv_bfloat16& lo) {
    hi = __float2bfloat16_rn(v);
    lo = __float2bfloat16_rn(v - __bfloat162float(hi));
}
static __device__ __forceinline__ float4 f4add(float4 a, float4 b) {
    return make_float4(a.x+b.x, a.y+b.y, a.z+b.z, a.w+b.w);
}

// ============================================================================
// K1: prep.
//   Blocks [0,512): blur with vertical register reuse.
//     out = wo * box3x3(x) + (ws-wo) * x[h-1][w-1]  (zero-padded)
//     thread = (b, w, c4) column, marches 16 rows; 3 loads/output.
//   Blocks [512,576): W = proj_w @ v_w.
// ============================================================================
__global__ __launch_bounds__(256) void prep_kernel(const float* __restrict__ x,
                                                   const float* __restrict__ vw,
                                                   const float* __restrict__ pw) {
    int bid = blockIdx.x;
    int tid = threadIdx.x;
    if (bid < 512) {
        int t  = bid * 256 + tid;
        int c4 = t & 63;
        int g  = t >> 6;          // (b, hseg, w)
        int w  = g & 63;
        int hs = (g >> 6) & 3;
        int b  = g >> 8;
        int h0 = hs * 16;
        const float e  = 2.718281828459045f;
        const float wo = 1.0f / (e + 8.0f);
        const float wd = e * wo - wo;          // ws - wo
        const float4* x4 = (const float4*)x;
        const float4 Z = make_float4(0.f, 0.f, 0.f, 0.f);
        size_t base = ((size_t)b * HH) * WW * 64 + c4;   // + r*WW*64 + w*64

        // load_row(r) -> (hsum, xl)
        auto load_row = [&](int r, float4& hsum, float4& xl) {
            if (r < 0 || r >= HH) { hsum = Z; xl = Z; return; }
            size_t rb = base + (size_t)r * WW * 64;
            xl = (w > 0)  ? x4[rb + (size_t)(w - 1) * 64] : Z;
            float4 xc =     x4[rb + (size_t)w * 64];
            float4 xr = (w < 63) ? x4[rb + (size_t)(w + 1) * 64] : Z;
            hsum = f4add(f4add(xl, xc), xr);
        };

        float4 hsA, xlA, hsB, xlB;
        load_row(h0 - 1, hsA, xlA);
        load_row(h0,     hsB, xlB);
        #pragma unroll
        for (int h = h0; h < h0 + 16; h++) {
            float4 hsC, xlC;
            load_row(h + 1, hsC, xlC);
            float4 o;
            o.x = wo * (hsA.x + hsB.x + hsC.x) + wd * xlA.x;
            o.y = wo * (hsA.y + hsB.y + hsC.y) + wd * xlA.y;
            o.z = wo * (hsA.z + hsB.z + hsC.z) + wd * xlA.z;
            o.w = wo * (hsA.w + hsB.w + hsC.w) + wd * xlA.w;
            union { __nv_bfloat16 h4[4]; uint2 u; } Hi, Lo;
            split_bf16(o.x, Hi.h4[0], Lo.h4[0]);
            split_bf16(o.y, Hi.h4[1], Lo.h4[1]);
            split_bf16(o.z, Hi.h4[2], Lo.h4[2]);
            split_bf16(o.w, Hi.h4[3], Lo.h4[3]);
            size_t oidx = (((size_t)b * HH + h) * WW + w) * 64 + c4;
            ((uint2*)g_yhi)[oidx] = Hi.u;
            ((uint2*)g_ylo)[oidx] = Lo.u;
            hsA = hsB; xlA = xlB; hsB = hsC; xlB = xlC;
        }
    } else {
        int q  = bid - 512;
        int e0 = (q >> 3) * 32;
        int c0 = (q & 7) * 32;
        int er = e0 + (tid >> 3);
        int cc = c0 + (tid & 7) * 4;
        float a0 = 0.f, a1 = 0.f, a2 = 0.f, a3 = 0.f;
        const float* prow = pw + er * 256;
        #pragma unroll 8
        for (int d = 0; d < 256; d++) {
            float a = prow[d];
            float4 v = *(const float4*)(vw + d * 256 + cc);
            a0 += a * v.x; a1 += a * v.y; a2 += a * v.z; a3 += a * v.w;
        }
        union { __nv_bfloat16 h4[4]; uint2 u; } Hi, Lo;
        split_bf16(a0, Hi.h4[0], Lo.h4[0]);
        split_bf16(a1, Hi.h4[1], Lo.h4[1]);
        split_bf16(a2, Hi.h4[2], Lo.h4[2]);
        split_bf16(a3, Hi.h4[3], Lo.h4[3]);
        int idx = er * 256 + cc;
        *(uint2*)(g_Whi + idx) = Hi.u;
        *(uint2*)(g_Wlo + idx) = Lo.u;
    }
}

// ============================================================================
// K2: out[m,n] = sum_k y[m,k]*W[n,k] + bias[n] via mma.sync bf16 (3 terms)
//     effective K = 768 over 24 chunks of 32; 4-stage cp.async ring;
//     CTA 128x128, 8 warps (4Mx2N), warp tile 32x64; one syncthreads/chunk.
// ============================================================================
#define STAGE_STRIDE 20480          // A(10240) + B(10240)
#define NSTAGE 4
#define SMEM_TOTAL (NSTAGE * STAGE_STRIDE)   // 80KB

__global__ __launch_bounds__(256) void gemm_mma_kernel(const float* __restrict__ bias,
                                                       float* __restrict__ out) {
    extern __shared__ __align__(16) char smem[];
    uint32_t sb = smem_u32(smem);
    int tid  = threadIdx.x;
    int wid  = tid >> 5;
    int lane = tid & 31;
    int bn = blockIdx.x * 128;
    int bm = blockIdx.y * 128;
    int wn = wid & 1;
    int wm = wid >> 1;

    float acc[2][8][4] = {};

    int ldrow = tid >> 1;
    int ldc8a = (tid & 1) * 2;

    auto issue_loads = [&](int pc, int slot) {
        int term = pc >> 3, kb = (pc & 7) * 32;
        const __nv_bfloat16* sA = (term == 1) ? g_ylo : g_yhi;
        const __nv_bfloat16* sB = (term == 2) ? g_Wlo : g_Whi;
        #pragma unroll
        for (int i = 0; i < 2; i++) {
            int c8 = ldc8a + i;
            uint64_t ga = gmem_u64(sA + (size_t)(bm + ldrow) * 256 + kb + c8 * 8);
            uint64_t gb = gmem_u64(sB + (size_t)(bn + ldrow) * 256 + kb + c8 * 8);
            uint32_t da = sb + slot * STAGE_STRIDE + ldrow * 80 + c8 * 16;
            CP_ASYNC16(da, ga);
            CP_ASYNC16(da + 10240, gb);
        }
    };

    // prologue: stages 0..2
    #pragma unroll
    for (int pc = 0; pc < 3; pc++) { issue_loads(pc, pc); CP_COMMIT(); }

    #pragma unroll 1
    for (int kc = 0; kc < 24; kc++) {
        CP_WAIT(2);
        __syncthreads();
        // issue next stage (or empty group to keep wait-count uniform)
        if (kc + 3 < 24) issue_loads(kc + 3, (kc + 3) & 3);
        CP_COMMIT();

        int slot = kc & 3;
        uint32_t aBase = sb + slot * STAGE_STRIDE;
        uint32_t bBase = aBase + 10240;

        #pragma unroll
        for (int ks = 0; ks < 2; ks++) {
            uint32_t af[2][4];
            #pragma unroll
            for (int mi = 0; mi < 2; mi++) {
                int row = wm * 32 + mi * 16 + (lane & 15);
                uint32_t addr = aBase + row * 80 + ks * 32 + (lane >> 4) * 16;
                LDMATRIX_X4(af[mi][0], af[mi][1], af[mi][2], af[mi][3], addr);
            }
            uint32_t bf[4][4];
            #pragma unroll
            for (int ng = 0; ng < 4; ng++) {
                int row = wn * 64 + ng * 16 + (lane & 15);
                uint32_t addr = bBase + row * 80 + ks * 32 + (lane >> 4) * 16;
                LDMATRIX_X4(bf[ng][0], bf[ng][1], bf[ng][2], bf[ng][3], addr);
            }
            #pragma unroll
            for (int mi = 0; mi < 2; mi++)
                #pragma unroll
                for (int ng = 0; ng < 4; ng++) {
                    MMA_16816(acc[mi][ng * 2 + 0], af[mi], bf[ng][0], bf[ng][2]);
                    MMA_16816(acc[mi][ng * 2 + 1], af[mi], bf[ng][1], bf[ng][3]);
                }
        }
    }

    // ---- epilogue ----
    #pragma unroll
    for (int mi = 0; mi < 2; mi++) {
        int r0 = bm + wm * 32 + mi * 16 + (lane >> 2);
        #pragma unroll
        for (int ni = 0; ni < 8; ni++) {
            int c = bn + wn * 64 + ni * 8 + (lane & 3) * 2;
            float b0 = __ldg(bias + c);
            float b1 = __ldg(bias + c + 1);
            float2 o0 = make_float2(acc[mi][ni][0] + b0, acc[mi][ni][1] + b1);
            float2 o1 = make_float2(acc[mi][ni][2] + b0, acc[mi][ni][3] + b1);
            *(float2*)(out + (size_t)r0 * 256 + c) = o0;
            *(float2*)(out + (size_t)(r0 + 8) * 256 + c) = o1;
        }
    }
}

// ============================================================================
extern "C" void kernel_launch(void* const* d_in, const int* in_sizes, int n_in,
                              void* d_out, int out_size) {
    const float* x  = (const float*)d_in[0];
    const float* vw = (const float*)d_in[1];
    const float* pw = (const float*)d_in[2];
    const float* pb = (const float*)d_in[3];
    float* out = (float*)d_out;

    cudaFuncSetAttribute(gemm_mma_kernel, cudaFuncAttributeMaxDynamicSharedMemorySize, SMEM_TOTAL);

    prep_kernel<<<512 + 64, 256>>>(x, vw, pw);
    gemm_mma_kernel<<<dim3(2, 256), 256, SMEM_TOTAL>>>(pb, out);
}

// round 5
// speedup vs baseline: 1.9414x; 1.1951x over previous
#include <cuda_runtime.h>
#include <cuda_bf16.h>
#include <stdint.h>
#include <math.h>

#define BB 8
#define HH 64
#define WW 64
#define CC 256
#define NPIX (BB*HH*WW)          // 32768

// ---------------- device scratch ----------------
__device__ __nv_bfloat16 g_yhi[NPIX*CC];
__device__ __nv_bfloat16 g_ylo[NPIX*CC];
__device__ __nv_bfloat16 g_Whi[CC*CC];
__device__ __nv_bfloat16 g_Wlo[CC*CC];

// ---------------- helpers ----------------
__device__ __forceinline__ uint32_t smem_u32(const void* p) {
    uint32_t a;
    asm("{ .reg .u64 t; cvta.to.shared.u64 t, %1; cvt.u32.u64 %0, t; }" : "=r"(a) : "l"(p));
    return a;
}
__device__ __forceinline__ uint64_t gmem_u64(const void* p) {
    uint64_t a;
    asm("cvta.to.global.u64 %0, %1;" : "=l"(a) : "l"(p));
    return a;
}
#define CP_ASYNC16(sa, ga) \
    asm volatile("cp.async.cg.shared.global [%0], [%1], 16;" :: "r"(sa), "l"(ga))
#define CP_COMMIT() asm volatile("cp.async.commit_group;")
#define CP_WAIT(n)  asm volatile("cp.async.wait_group %0;" :: "n"(n))

#define LDMATRIX_X4(r0, r1, r2, r3, addr) \
    asm volatile("ldmatrix.sync.aligned.m8n8.x4.shared.b16 {%0,%1,%2,%3}, [%4];" \
        : "=r"(r0), "=r"(r1), "=r"(r2), "=r"(r3) : "r"(addr))

#define MMA_16816(c, a, b0, b1) \
    asm volatile("mma.sync.aligned.m16n8k16.row.col.f32.bf16.bf16.f32 " \
        "{%0,%1,%2,%3}, {%4,%5,%6,%7}, {%8,%9}, {%0,%1,%2,%3};" \
        : "+f"((c)[0]), "+f"((c)[1]), "+f"((c)[2]), "+f"((c)[3]) \
        : "r"((a)[0]), "r"((a)[1]), "r"((a)[2]), "r"((a)[3]), "r"(b0), "r"(b1))

static __device__ __forceinline__ void split_bf16(float v, __nv_bfloat16& hi, __nv_bfloat16& lo) {
    hi = __float2bfloat16_rn(v);
    lo = __float2bfloat16_rn(v - __bfloat162float(hi));
}
static __device__ __forceinline__ float4 f4add(float4 a, float4 b) {
    return make_float4(a.x+b.x, a.y+b.y, a.z+b.z, a.w+b.w);
}

// ============================================================================
// K1: prep.
//  Blocks [0,256): blur, smem row-sharing. Block = (b, 16-row hseg, 8-c4 cgroup),
//    all 64 w. Each input row staged once in smem (2-row ring, 1 bar/row);
//    per-thread 3-row hsum ring in registers. x read ~1x.
//  Blocks [256,320): W = proj_w @ v_w -> (g_Whi, g_Wlo).
// ============================================================================
__global__ __launch_bounds__(256) void prep_kernel(const float* __restrict__ x,
                                                   const float* __restrict__ vw,
                                                   const float* __restrict__ pw) {
    __shared__ float4 srow[2 * 64 * 9];   // 2 slots x 64 w x 8 c4 (stride 9) = 18KB
    int bid = blockIdx.x;
    int tid = threadIdx.x;
    if (bid < 256) {
        int b  = bid >> 5;
        int hs = (bid >> 3) & 3;
        int cg = bid & 7;
        int h0 = hs * 16;
        int w     = tid >> 2;         // 0..63
        int cpair = (tid & 3) * 2;    // items: c = cpair, cpair+1 (within cgroup)
        int lc = tid & 7;             // load mapping
        int lw = tid >> 3;            // 0..31 (two w per thread: lw, lw+32)
        const float e  = 2.718281828459045f;
        const float wo = 1.0f / (e + 8.0f);
        const float wd = e * wo - wo;
        const float4 Z = make_float4(0.f, 0.f, 0.f, 0.f);
        const float4* x4 = (const float4*)x;
        size_t bbase = (size_t)b * HH * WW * 64 + cg * 8;

        float4 hs3[3][2], xl3[3][2];
        #pragma unroll
        for (int s = 0; s < 3; s++)
            #pragma unroll
            for (int it = 0; it < 2; it++) { hs3[s][it] = Z; xl3[s][it] = Z; }

        #pragma unroll 1
        for (int r = h0 - 1; r <= h0 + 16; r++) {
            int slot = (r - (h0 - 1)) & 1;
            float4 v0 = Z, v1 = Z;
            if (r >= 0 && r < HH) {
                size_t rb = bbase + (size_t)r * WW * 64;
                v0 = x4[rb + (size_t)lw * 64 + lc];
                v1 = x4[rb + (size_t)(lw + 32) * 64 + lc];
            }
            srow[slot * 576 + lw * 9 + lc] = v0;
            srow[slot * 576 + (lw + 32) * 9 + lc] = v1;
            __syncthreads();

            // compute row-r horizontal sums for this thread's 2 items
            #pragma unroll
            for (int it = 0; it < 2; it++) {
                int c = cpair + it;
                float4 xl = (w > 0)  ? srow[slot * 576 + (w - 1) * 9 + c] : Z;
                float4 xc =            srow[slot * 576 + w * 9 + c];
                float4 xr = (w < 63) ? srow[slot * 576 + (w + 1) * 9 + c] : Z;
                hs3[2][it] = f4add(f4add(xl, xc), xr);
                xl3[2][it] = xl;
            }

            if (r >= h0 + 1) {
                int h = r - 1;
                #pragma unroll
                for (int it = 0; it < 2; it++) {
                    float4 o;
                    o.x = wo * (hs3[0][it].x + hs3[1][it].x + hs3[2][it].x) + wd * xl3[0][it].x;
                    o.y = wo * (hs3[0][it].y + hs3[1][it].y + hs3[2][it].y) + wd * xl3[0][it].y;
                    o.z = wo * (hs3[0][it].z + hs3[1][it].z + hs3[2][it].z) + wd * xl3[0][it].z;
                    o.w = wo * (hs3[0][it].w + hs3[1][it].w + hs3[2][it].w) + wd * xl3[0][it].w;
                    union { __nv_bfloat16 h4[4]; uint2 u; } Hi, Lo;
                    split_bf16(o.x, Hi.h4[0], Lo.h4[0]);
                    split_bf16(o.y, Hi.h4[1], Lo.h4[1]);
                    split_bf16(o.z, Hi.h4[2], Lo.h4[2]);
                    split_bf16(o.w, Hi.h4[3], Lo.h4[3]);
                    size_t oidx = (((size_t)b * HH + h) * WW + w) * 64 + cg * 8 + cpair + it;
                    ((uint2*)g_yhi)[oidx] = Hi.u;
                    ((uint2*)g_ylo)[oidx] = Lo.u;
                }
            }
            // shift ring
            #pragma unroll
            for (int it = 0; it < 2; it++) {
                hs3[0][it] = hs3[1][it]; xl3[0][it] = xl3[1][it];
                hs3[1][it] = hs3[2][it]; xl3[1][it] = xl3[2][it];
            }
        }
    } else {
        int q  = bid - 256;
        int e0 = (q >> 3) * 32;
        int c0 = (q & 7) * 32;
        int er = e0 + (tid >> 3);
        int cc = c0 + (tid & 7) * 4;
        float a0 = 0.f, a1 = 0.f, a2 = 0.f, a3 = 0.f;
        const float* prow = pw + er * 256;
        #pragma unroll 8
        for (int d = 0; d < 256; d++) {
            float a = prow[d];
            float4 v = *(const float4*)(vw + d * 256 + cc);
            a0 += a * v.x; a1 += a * v.y; a2 += a * v.z; a3 += a * v.w;
        }
        union { __nv_bfloat16 h4[4]; uint2 u; } Hi, Lo;
        split_bf16(a0, Hi.h4[0], Lo.h4[0]);
        split_bf16(a1, Hi.h4[1], Lo.h4[1]);
        split_bf16(a2, Hi.h4[2], Lo.h4[2]);
        split_bf16(a3, Hi.h4[3], Lo.h4[3]);
        int idx = er * 256 + cc;
        *(uint2*)(g_Whi + idx) = Hi.u;
        *(uint2*)(g_Wlo + idx) = Lo.u;
    }
}

// ============================================================================
// K2: out = y @ W^T + bias, bf16 3-term split, FUSED chunks:
//   8 physical K-chunks of 32; per chunk load Ahi,Alo,Bhi,Blo once,
//   run 3 MMA terms (Ahi*Bhi, Alo*Bhi, Ahi*Blo) = 96 HMMA per warp per chunk.
//   CTA 128x128, 8 warps (4Mx2N), warp tile 32x64, 2-stage cp.async ring.
//   B-fragment registers reused between Bhi and Blo passes.
// ============================================================================
#define MAT_STRIDE 10240            // 128 rows * 80B
#define STG (4 * MAT_STRIDE)        // Ahi,Alo,Bhi,Blo per stage = 40KB
#define SMEM_TOTAL (2 * STG)        // 80KB

__global__ __launch_bounds__(256, 2) void gemm_mma_kernel(const float* __restrict__ bias,
                                                          float* __restrict__ out) {
    extern __shared__ __align__(16) char smem[];
    uint32_t sb = smem_u32(smem);
    int tid  = threadIdx.x;
    int wid  = tid >> 5;
    int lane = tid & 31;
    int bn = blockIdx.x * 128;
    int bm = blockIdx.y * 128;
    int wn = wid & 1;
    int wm = wid >> 1;

    float acc[2][8][4] = {};

    int ldrow = tid >> 1;
    int ldc8a = (tid & 1) * 2;

    auto issue_loads = [&](int kc2, int slot) {
        int kb = kc2 * 32;
        #pragma unroll
        for (int i = 0; i < 2; i++) {
            int c8 = ldc8a + i;
            size_t aoff = (size_t)(bm + ldrow) * 256 + kb + c8 * 8;
            size_t boff = (size_t)(bn + ldrow) * 256 + kb + c8 * 8;
            uint32_t da = sb + slot * STG + ldrow * 80 + c8 * 16;
            CP_ASYNC16(da,                  gmem_u64(g_yhi + aoff));
            CP_ASYNC16(da + MAT_STRIDE,     gmem_u64(g_ylo + aoff));
            CP_ASYNC16(da + 2 * MAT_STRIDE, gmem_u64(g_Whi + boff));
            CP_ASYNC16(da + 3 * MAT_STRIDE, gmem_u64(g_Wlo + boff));
        }
    };

    issue_loads(0, 0); CP_COMMIT();
    issue_loads(1, 1); CP_COMMIT();

    #pragma unroll 1
    for (int kc = 0; kc < 8; kc++) {
        CP_WAIT(1);
        __syncthreads();

        int slot = kc & 1;
        uint32_t aHi = sb + slot * STG;
        uint32_t aLo = aHi + MAT_STRIDE;
        uint32_t bHi = aHi + 2 * MAT_STRIDE;
        uint32_t bLo = aHi + 3 * MAT_STRIDE;

        #pragma unroll
        for (int ks = 0; ks < 2; ks++) {
            uint32_t afh[2][4], afl[2][4], bf[4][4];
            #pragma unroll
            for (int mi = 0; mi < 2; mi++) {
                int row = wm * 32 + mi * 16 + (lane & 15);
                uint32_t ao = row * 80 + ks * 32 + (lane >> 4) * 16;
                LDMATRIX_X4(afh[mi][0], afh[mi][1], afh[mi][2], afh[mi][3], aHi + ao);
                LDMATRIX_X4(afl[mi][0], afl[mi][1], afl[mi][2], afl[mi][3], aLo + ao);
            }
            #pragma unroll
            for (int ng = 0; ng < 4; ng++) {
                int row = wn * 64 + ng * 16 + (lane & 15);
                uint32_t bo = row * 80 + ks * 32 + (lane >> 4) * 16;
                LDMATRIX_X4(bf[ng][0], bf[ng][1], bf[ng][2], bf[ng][3], bHi + bo);
            }
            #pragma unroll
            for (int mi = 0; mi < 2; mi++)
                #pragma unroll
                for (int ng = 0; ng < 4; ng++) {
                    MMA_16816(acc[mi][ng * 2 + 0], afh[mi], bf[ng][0], bf[ng][2]);
                    MMA_16816(acc[mi][ng * 2 + 1], afh[mi], bf[ng][1], bf[ng][3]);
                    MMA_16816(acc[mi][ng * 2 + 0], afl[mi], bf[ng][0], bf[ng][2]);
                    MMA_16816(acc[mi][ng * 2 + 1], afl[mi], bf[ng][1], bf[ng][3]);
                }
            // reload B registers with Blo, run term 2 (Ahi * Blo)
            #pragma unroll
            for (int ng = 0; ng < 4; ng++) {
                int row = wn * 64 + ng * 16 + (lane & 15);
                uint32_t bo = row * 80 + ks * 32 + (lane >> 4) * 16;
                LDMATRIX_X4(bf[ng][0], bf[ng][1], bf[ng][2], bf[ng][3], bLo + bo);
            }
            #pragma unroll
            for (int mi = 0; mi < 2; mi++)
                #pragma unroll
                for (int ng = 0; ng < 4; ng++) {
                    MMA_16816(acc[mi][ng * 2 + 0], afh[mi], bf[ng][0], bf[ng][2]);
                    MMA_16816(acc[mi][ng * 2 + 1], afh[mi], bf[ng][1], bf[ng][3]);
                }
        }
        __syncthreads();
        if (kc + 2 < 8) issue_loads(kc + 2, slot);
        CP_COMMIT();
    }

    // ---- epilogue ----
    #pragma unroll
    for (int mi = 0; mi < 2; mi++) {
        int r0 = bm + wm * 32 + mi * 16 + (lane >> 2);
        #pragma unroll
        for (int ni = 0; ni < 8; ni++) {
            int c = bn + wn * 64 + ni * 8 + (lane & 3) * 2;
            float b0 = __ldg(bias + c);
            float b1 = __ldg(bias + c + 1);
            float2 o0 = make_float2(acc[mi][ni][0] + b0, acc[mi][ni][1] + b1);
            float2 o1 = make_float2(acc[mi][ni][2] + b0, acc[mi][ni][3] + b1);
            *(float2*)(out + (size_t)r0 * 256 + c) = o0;
            *(float2*)(out + (size_t)(r0 + 8) * 256 + c) = o1;
        }
    }
}

// ============================================================================
extern "C" void kernel_launch(void* const* d_in, const int* in_sizes, int n_in,
                              void* d_out, int out_size) {
    const float* x  = (const float*)d_in[0];
    const float* vw = (const float*)d_in[1];
    const float* pw = (const float*)d_in[2];
    const float* pb = (const float*)d_in[3];
    float* out = (float*)d_out;

    cudaFuncSetAttribute(gemm_mma_kernel, cudaFuncAttributeMaxDynamicSharedMemorySize, SMEM_TOTAL);

    prep_kernel<<<256 + 64, 256>>>(x, vw, pw);
    gemm_mma_kernel<<<dim3(2, 256), 256, SMEM_TOTAL>>>(pb, out);
}

// round 6
// speedup vs baseline: 1.9545x; 1.0067x over previous
#include <cuda_runtime.h>
#include <cuda_bf16.h>
#include <stdint.h>
#include <math.h>

#define BB 8
#define HH 64
#define WW 64
#define CC 256
#define NPIX (BB*HH*WW)          // 32768

// ---------------- device scratch ----------------
__device__ __nv_bfloat16 g_yhi[NPIX*CC];
__device__ __nv_bfloat16 g_ylo[NPIX*CC];
__device__ __nv_bfloat16 g_Whi[CC*CC];
__device__ __nv_bfloat16 g_Wlo[CC*CC];

// ---------------- helpers ----------------
__device__ __forceinline__ uint32_t smem_u32(const void* p) {
    uint32_t a;
    asm("{ .reg .u64 t; cvta.to.shared.u64 t, %1; cvt.u32.u64 %0, t; }" : "=r"(a) : "l"(p));
    return a;
}
__device__ __forceinline__ uint64_t gmem_u64(const void* p) {
    uint64_t a;
    asm("cvta.to.global.u64 %0, %1;" : "=l"(a) : "l"(p));
    return a;
}
#define CP_ASYNC16(sa, ga) \
    asm volatile("cp.async.cg.shared.global [%0], [%1], 16;" :: "r"(sa), "l"(ga))
#define CP_COMMIT() asm volatile("cp.async.commit_group;")
#define CP_WAIT(n)  asm volatile("cp.async.wait_group %0;" :: "n"(n))

#define LDMATRIX_X4(r0, r1, r2, r3, addr) \
    asm volatile("ldmatrix.sync.aligned.m8n8.x4.shared.b16 {%0,%1,%2,%3}, [%4];" \
        : "=r"(r0), "=r"(r1), "=r"(r2), "=r"(r3) : "r"(addr))

#define MMA_16816(c, a, b0, b1) \
    asm volatile("mma.sync.aligned.m16n8k16.row.col.f32.bf16.bf16.f32 " \
        "{%0,%1,%2,%3}, {%4,%5,%6,%7}, {%8,%9}, {%0,%1,%2,%3};" \
        : "+f"((c)[0]), "+f"((c)[1]), "+f"((c)[2]), "+f"((c)[3]) \
        : "r"((a)[0]), "r"((a)[1]), "r"((a)[2]), "r"((a)[3]), "r"(b0), "r"(b1))

static __device__ __forceinline__ void split_bf16(float v, __nv_bfloat16& hi, __nv_bfloat16& lo) {
    hi = __float2bfloat16_rn(v);
    lo = __float2bfloat16_rn(v - __bfloat162float(hi));
}
static __device__ __forceinline__ float4 f4add(float4 a, float4 b) {
    return make_float4(a.x+b.x, a.y+b.y, a.z+b.z, a.w+b.w);
}

// ============================================================================
// K1: prep.
//  Blocks [0,256): blur with smem row-sharing + register prefetch of next row.
//  Blocks [256,320): W = proj_w @ v_w -> (g_Whi, g_Wlo).
// ============================================================================
__global__ __launch_bounds__(256) void prep_kernel(const float* __restrict__ x,
                                                   const float* __restrict__ vw,
                                                   const float* __restrict__ pw) {
    __shared__ float4 srow[2 * 64 * 9];   // 2 slots x 64 w x 8 c4 (stride 9)
    int bid = blockIdx.x;
    int tid = threadIdx.x;
    if (bid < 256) {
        int b  = bid >> 5;
        int hs = (bid >> 3) & 3;
        int cg = bid & 7;
        int h0 = hs * 16;
        int w     = tid >> 2;
        int cpair = (tid & 3) * 2;
        int lc = tid & 7;
        int lw = tid >> 3;
        const float e  = 2.718281828459045f;
        const float wo = 1.0f / (e + 8.0f);
        const float wd = e * wo - wo;
        const float4 Z = make_float4(0.f, 0.f, 0.f, 0.f);
        const float4* x4 = (const float4*)x;
        size_t bbase = (size_t)b * HH * WW * 64 + cg * 8;

        auto gload = [&](int r, float4& a, float4& bb) {
            if (r >= 0 && r < HH) {
                size_t rb = bbase + (size_t)r * WW * 64;
                a  = x4[rb + (size_t)lw * 64 + lc];
                bb = x4[rb + (size_t)(lw + 32) * 64 + lc];
            } else { a = Z; bb = Z; }
        };

        float4 hs3[3][2], xl3[3][2];
        #pragma unroll
        for (int s = 0; s < 3; s++)
            #pragma unroll
            for (int it = 0; it < 2; it++) { hs3[s][it] = Z; xl3[s][it] = Z; }

        float4 vn0, vn1;
        gload(h0 - 1, vn0, vn1);     // prefetch first row

        #pragma unroll 1
        for (int r = h0 - 1; r <= h0 + 16; r++) {
            int slot = (r - (h0 - 1)) & 1;
            float4 v0 = vn0, v1 = vn1;
            if (r < h0 + 16) gload(r + 1, vn0, vn1);   // prefetch next (overlaps below)
            srow[slot * 576 + lw * 9 + lc] = v0;
            srow[slot * 576 + (lw + 32) * 9 + lc] = v1;
            __syncthreads();

            #pragma unroll
            for (int it = 0; it < 2; it++) {
                int c = cpair + it;
                float4 xl = (w > 0)  ? srow[slot * 576 + (w - 1) * 9 + c] : Z;
                float4 xc =            srow[slot * 576 + w * 9 + c];
                float4 xr = (w < 63) ? srow[slot * 576 + (w + 1) * 9 + c] : Z;
                hs3[2][it] = f4add(f4add(xl, xc), xr);
                xl3[2][it] = xl;
            }

            if (r >= h0 + 1) {
                int h = r - 1;
                #pragma unroll
                for (int it = 0; it < 2; it++) {
                    float4 o;
                    o.x = wo * (hs3[0][it].x + hs3[1][it].x + hs3[2][it].x) + wd * xl3[0][it].x;
                    o.y = wo * (hs3[0][it].y + hs3[1][it].y + hs3[2][it].y) + wd * xl3[0][it].y;
                    o.z = wo * (hs3[0][it].z + hs3[1][it].z + hs3[2][it].z) + wd * xl3[0][it].z;
                    o.w = wo * (hs3[0][it].w + hs3[1][it].w + hs3[2][it].w) + wd * xl3[0][it].w;
                    union { __nv_bfloat16 h4[4]; uint2 u; } Hi, Lo;
                    split_bf16(o.x, Hi.h4[0], Lo.h4[0]);
                    split_bf16(o.y, Hi.h4[1], Lo.h4[1]);
                    split_bf16(o.z, Hi.h4[2], Lo.h4[2]);
                    split_bf16(o.w, Hi.h4[3], Lo.h4[3]);
                    size_t oidx = (((size_t)b * HH + h) * WW + w) * 64 + cg * 8 + cpair + it;
                    ((uint2*)g_yhi)[oidx] = Hi.u;
                    ((uint2*)g_ylo)[oidx] = Lo.u;
                }
            }
            #pragma unroll
            for (int it = 0; it < 2; it++) {
                hs3[0][it] = hs3[1][it]; xl3[0][it] = xl3[1][it];
                hs3[1][it] = hs3[2][it]; xl3[1][it] = xl3[2][it];
            }
        }
    } else {
        int q  = bid - 256;
        int e0 = (q >> 3) * 32;
        int c0 = (q & 7) * 32;
        int er = e0 + (tid >> 3);
        int cc = c0 + (tid & 7) * 4;
        float a0 = 0.f, a1 = 0.f, a2 = 0.f, a3 = 0.f;
        const float* prow = pw + er * 256;
        #pragma unroll 8
        for (int d = 0; d < 256; d++) {
            float a = prow[d];
            float4 v = *(const float4*)(vw + d * 256 + cc);
            a0 += a * v.x; a1 += a * v.y; a2 += a * v.z; a3 += a * v.w;
        }
        union { __nv_bfloat16 h4[4]; uint2 u; } Hi, Lo;
        split_bf16(a0, Hi.h4[0], Lo.h4[0]);
        split_bf16(a1, Hi.h4[1], Lo.h4[1]);
        split_bf16(a2, Hi.h4[2], Lo.h4[2]);
        split_bf16(a3, Hi.h4[3], Lo.h4[3]);
        int idx = er * 256 + cc;
        *(uint2*)(g_Whi + idx) = Hi.u;
        *(uint2*)(g_Wlo + idx) = Lo.u;
    }
}

// ============================================================================
// K2: out = y @ W^T + bias, bf16 3-term split, fused chunks, TERM-MAJOR MMA
//   ordering (acc RAW distance 16 instead of 2).
//   CTA 128x128, 8 warps (4Mx2N), warp tile 32x64, 2-stage cp.async ring.
// ============================================================================
#define MAT_STRIDE 10240            // 128 rows * 80B
#define STG (4 * MAT_STRIDE)        // Ahi,Alo,Bhi,Blo per stage = 40KB
#define SMEM_TOTAL (2 * STG)        // 80KB

__global__ __launch_bounds__(256, 2) void gemm_mma_kernel(const float* __restrict__ bias,
                                                          float* __restrict__ out) {
    extern __shared__ __align__(16) char smem[];
    uint32_t sb = smem_u32(smem);
    int tid  = threadIdx.x;
    int wid  = tid >> 5;
    int lane = tid & 31;
    int bn = blockIdx.x * 128;
    int bm = blockIdx.y * 128;
    int wn = wid & 1;
    int wm = wid >> 1;

    float acc[2][8][4] = {};

    int ldrow = tid >> 1;
    int ldc8a = (tid & 1) * 2;

    auto issue_loads = [&](int kc2, int slot) {
        int kb = kc2 * 32;
        #pragma unroll
        for (int i = 0; i < 2; i++) {
            int c8 = ldc8a + i;
            size_t aoff = (size_t)(bm + ldrow) * 256 + kb + c8 * 8;
            size_t boff = (size_t)(bn + ldrow) * 256 + kb + c8 * 8;
            uint32_t da = sb + slot * STG + ldrow * 80 + c8 * 16;
            CP_ASYNC16(da,                  gmem_u64(g_yhi + aoff));
            CP_ASYNC16(da + MAT_STRIDE,     gmem_u64(g_ylo + aoff));
            CP_ASYNC16(da + 2 * MAT_STRIDE, gmem_u64(g_Whi + boff));
            CP_ASYNC16(da + 3 * MAT_STRIDE, gmem_u64(g_Wlo + boff));
        }
    };

    issue_loads(0, 0); CP_COMMIT();
    issue_loads(1, 1); CP_COMMIT();

    #pragma unroll 1
    for (int kc = 0; kc < 8; kc++) {
        CP_WAIT(1);
        __syncthreads();

        int slot = kc & 1;
        uint32_t aHi = sb + slot * STG;
        uint32_t aLo = aHi + MAT_STRIDE;
        uint32_t bHi = aHi + 2 * MAT_STRIDE;
        uint32_t bLo = aHi + 3 * MAT_STRIDE;

        #pragma unroll
        for (int ks = 0; ks < 2; ks++) {
            uint32_t afh[2][4], afl[2][4], bf[4][4];
            #pragma unroll
            for (int mi = 0; mi < 2; mi++) {
                int row = wm * 32 + mi * 16 + (lane & 15);
                uint32_t ao = row * 80 + ks * 32 + (lane >> 4) * 16;
                LDMATRIX_X4(afh[mi][0], afh[mi][1], afh[mi][2], afh[mi][3], aHi + ao);
                LDMATRIX_X4(afl[mi][0], afl[mi][1], afl[mi][2], afl[mi][3], aLo + ao);
            }
            #pragma unroll
            for (int ng = 0; ng < 4; ng++) {
                int row = wn * 64 + ng * 16 + (lane & 15);
                uint32_t bo = row * 80 + ks * 32 + (lane >> 4) * 16;
                LDMATRIX_X4(bf[ng][0], bf[ng][1], bf[ng][2], bf[ng][3], bHi + bo);
            }
            // term0: Ahi * Bhi  (16 MMAs, all-distinct accumulators)
            #pragma unroll
            for (int mi = 0; mi < 2; mi++)
                #pragma unroll
                for (int ng = 0; ng < 4; ng++) {
                    MMA_16816(acc[mi][ng * 2 + 0], afh[mi], bf[ng][0], bf[ng][2]);
                    MMA_16816(acc[mi][ng * 2 + 1], afh[mi], bf[ng][1], bf[ng][3]);
                }
            // term1: Alo * Bhi  (RAW distance 16 from term0)
            #pragma unroll
            for (int mi = 0; mi < 2; mi++)
                #pragma unroll
                for (int ng = 0; ng < 4; ng++) {
                    MMA_16816(acc[mi][ng * 2 + 0], afl[mi], bf[ng][0], bf[ng][2]);
                    MMA_16816(acc[mi][ng * 2 + 1], afl[mi], bf[ng][1], bf[ng][3]);
                }
            // reload B with Blo
            #pragma unroll
            for (int ng = 0; ng < 4; ng++) {
                int row = wn * 64 + ng * 16 + (lane & 15);
                uint32_t bo = row * 80 + ks * 32 + (lane >> 4) * 16;
                LDMATRIX_X4(bf[ng][0], bf[ng][1], bf[ng][2], bf[ng][3], bLo + bo);
            }
            // term2: Ahi * Blo
            #pragma unroll
            for (int mi = 0; mi < 2; mi++)
                #pragma unroll
                for (int ng = 0; ng < 4; ng++) {
                    MMA_16816(acc[mi][ng * 2 + 0], afh[mi], bf[ng][0], bf[ng][2]);
                    MMA_16816(acc[mi][ng * 2 + 1], afh[mi], bf[ng][1], bf[ng][3]);
                }
        }
        __syncthreads();
        if (kc + 2 < 8) issue_loads(kc + 2, slot);
        CP_COMMIT();
    }

    // ---- epilogue ----
    #pragma unroll
    for (int mi = 0; mi < 2; mi++) {
        int r0 = bm + wm * 32 + mi * 16 + (lane >> 2);
        #pragma unroll
        for (int ni = 0; ni < 8; ni++) {
            int c = bn + wn * 64 + ni * 8 + (lane & 3) * 2;
            float b0 = __ldg(bias + c);
            float b1 = __ldg(bias + c + 1);
            float2 o0 = make_float2(acc[mi][ni][0] + b0, acc[mi][ni][1] + b1);
            float2 o1 = make_float2(acc[mi][ni][2] + b0, acc[mi][ni][3] + b1);
            *(float2*)(out + (size_t)r0 * 256 + c) = o0;
            *(float2*)(out + (size_t)(r0 + 8) * 256 + c) = o1;
        }
    }
}

// ============================================================================
extern "C" void kernel_launch(void* const* d_in, const int* in_sizes, int n_in,
                              void* d_out, int out_size) {
    const float* x  = (const float*)d_in[0];
    const float* vw = (const float*)d_in[1];
    const float* pw = (const float*)d_in[2];
    const float* pb = (const float*)d_in[3];
    float* out = (float*)d_out;

    cudaFuncSetAttribute(gemm_mma_kernel, cudaFuncAttributeMaxDynamicSharedMemorySize, SMEM_TOTAL);

    prep_kernel<<<256 + 64, 256>>>(x, vw, pw);
    gemm_mma_kernel<<<dim3(2, 256), 256, SMEM_TOTAL>>>(pb, out);
}